// round 3
// baseline (speedup 1.0000x reference)
#include <cuda_runtime.h>
#include <cuda_bf16.h>
#include <math.h>

#define N_NODES_MAX 100000
#define D_IN        256
#define H1          16
#define H2          32

// Scratch (device globals — BSS zero-init; every call leaves them zeroed again,
// so the kernel is deterministic across graph replays).
__device__ __align__(256) float g_y[N_NODES_MAX * H1];   // x @ W1
__device__ __align__(256) float g_a[N_NODES_MAX * H1];   // spmm accumulator (pre-relu)
__device__ __align__(256) float g_s[N_NODES_MAX];        // s[j] = sum_{e: col==j} val[e]
__device__ __align__(256) float g_t[H1];                 // t = sum_i s[i]*relu(a[i])
__device__ unsigned g_ticket;                            // last-block ticket

// ---------------------------------------------------------------------------
// y = x @ W1   (N x 256) @ (256 x 16). Thread per row; W1 in shared.
// Also accumulates s[c] += v (L2 atomics hide under the DRAM stream).
// ---------------------------------------------------------------------------
__global__ void gemm1_kernel(const float* __restrict__ x,
                             const float* __restrict__ W1, int n,
                             const int* __restrict__ cols,
                             const float* __restrict__ vals, int e_count) {
    __shared__ float4 sW[D_IN * H1 / 4];  // 1024 float4 = 16KB
    for (int i = threadIdx.x; i < D_IN * H1 / 4; i += blockDim.x)
        sW[i] = reinterpret_cast<const float4*>(W1)[i];
    __syncthreads();

    int tid0 = blockIdx.x * blockDim.x + threadIdx.x;
    int stride = gridDim.x * blockDim.x;

    // s accumulation (g_s is zero on entry: BSS / self-cleaned by reduce pass)
    for (int e = tid0; e < e_count; e += stride) {
        atomicAdd(&g_s[__ldg(cols + e)], __ldg(vals + e));
    }

    const float4 z4 = {0.f, 0.f, 0.f, 0.f};
    for (int row = tid0; row < n; row += stride) {
        const float4* xr = reinterpret_cast<const float4*>(x + (size_t)row * D_IN);
        float4 acc0 = z4, acc1 = z4, acc2 = z4, acc3 = z4;
#pragma unroll 8
        for (int k4 = 0; k4 < D_IN / 4; k4++) {
            float4 xv = xr[k4];
#pragma unroll
            for (int kk = 0; kk < 4; kk++) {
                float xs = (kk == 0) ? xv.x : (kk == 1) ? xv.y : (kk == 2) ? xv.z : xv.w;
                int k = 4 * k4 + kk;
                float4 w0 = sW[k * 4 + 0];
                float4 w1 = sW[k * 4 + 1];
                float4 w2 = sW[k * 4 + 2];
                float4 w3 = sW[k * 4 + 3];
                acc0.x += xs * w0.x; acc0.y += xs * w0.y; acc0.z += xs * w0.z; acc0.w += xs * w0.w;
                acc1.x += xs * w1.x; acc1.y += xs * w1.y; acc1.z += xs * w1.z; acc1.w += xs * w1.w;
                acc2.x += xs * w2.x; acc2.y += xs * w2.y; acc2.z += xs * w2.z; acc2.w += xs * w2.w;
                acc3.x += xs * w3.x; acc3.y += xs * w3.y; acc3.z += xs * w3.z; acc3.w += xs * w3.w;
            }
        }
        float4* yr = reinterpret_cast<float4*>(g_y + (size_t)row * H1);
        yr[0] = acc0; yr[1] = acc1; yr[2] = acc2; yr[3] = acc3;
    }
}

// ---------------------------------------------------------------------------
// Edge pass: a[r] += v * y[c] via red.global.add.v4.f32 (4 lanes per edge)
// ---------------------------------------------------------------------------
__global__ void edge_kernel(const int* __restrict__ rows,
                            const int* __restrict__ cols,
                            const float* __restrict__ vals, int e_count) {
    int gid = blockIdx.x * blockDim.x + threadIdx.x;
    int q = gid & 3;           // quarter of the 16-wide feature row
    int e = gid >> 2;
    if (e >= e_count) return;

    int r = __ldg(rows + e);
    int c = __ldg(cols + e);
    float v = __ldg(vals + e);

    const float4 yv = __ldg(reinterpret_cast<const float4*>(g_y + (size_t)c * H1 + q * 4));
    float px = v * yv.x, py = v * yv.y, pz = v * yv.z, pw = v * yv.w;
    float* dst = g_a + (size_t)r * H1 + q * 4;
    asm volatile("red.global.add.v4.f32 [%0], {%1, %2, %3, %4};"
                 :: "l"(dst), "f"(px), "f"(py), "f"(pz), "f"(pw) : "memory");
}

// ---------------------------------------------------------------------------
// t[f] = sum_i s[i] * relu(a[i][f]); self-cleans g_a/g_s; last block computes
// the final output and cleans g_t/g_ticket.
// NOTE: requires (n*4) % 32 == 0 and stride % 32 == 0 so warps have uniform
// trip counts (n = 100000 -> 400000 ok).
// ---------------------------------------------------------------------------
__global__ void reduce_final_kernel(int n,
                                    const float* __restrict__ W2,
                                    const float* __restrict__ w_out,
                                    const float* __restrict__ b_out,
                                    float* __restrict__ out) {
    __shared__ float4 red[256];
    __shared__ bool is_last;
    int tid = threadIdx.x;
    int g = tid & 3;  // feature group: covers features [4g, 4g+4)
    const float4 z4 = {0.f, 0.f, 0.f, 0.f};
    float4 acc = z4;
    int total = n * 4;
    int stride = gridDim.x * blockDim.x;
    for (int idx = blockIdx.x * blockDim.x + tid; idx < total; idx += stride) {
        int i = idx >> 2;
        float4* ap = reinterpret_cast<float4*>(g_a + (size_t)i * H1 + g * 4);
        float4 av = *ap;
        float s = 0.0f;
        if (g == 0) { s = g_s[i]; g_s[i] = 0.0f; }   // sole reader of g_s[i]
        s = __shfl_sync(0xffffffffu, s, (tid & 31) & ~3);
        *ap = z4;                                     // self-clean g_a
        acc.x += s * fmaxf(av.x, 0.f);
        acc.y += s * fmaxf(av.y, 0.f);
        acc.z += s * fmaxf(av.z, 0.f);
        acc.w += s * fmaxf(av.w, 0.f);
    }
    red[tid] = acc;
    __syncthreads();
#pragma unroll
    for (int off = 128; off >= 4; off >>= 1) {
        if (tid < off) {
            float4 o = red[tid + off];
            red[tid].x += o.x; red[tid].y += o.y; red[tid].z += o.z; red[tid].w += o.w;
        }
        __syncthreads();
    }
    if (tid < 4) {
        float4 r4 = red[tid];
        float* dst = g_t + tid * 4;
        asm volatile("red.global.add.v4.f32 [%0], {%1, %2, %3, %4};"
                     :: "l"(dst), "f"(r4.x), "f"(r4.y), "f"(r4.z), "f"(r4.w) : "memory");
    }
    __threadfence();
    if (tid == 0) {
        unsigned done = atomicAdd(&g_ticket, 1u);
        is_last = (done == gridDim.x - 1);
    }
    __syncthreads();
    if (is_last) {
        __threadfence();  // pair with producers' fences
        float z = 0.0f;
        if (tid < H2) {
#pragma unroll
            for (int fi = 0; fi < H1; fi++) z += g_t[fi] * W2[fi * H2 + tid];
        }
        __syncthreads();
        if (tid < H1) g_t[tid] = 0.0f;   // self-clean g_t
        if (tid == 0) g_ticket = 0u;     // self-clean ticket
        if (tid < H2) {
            float p = z * w_out[tid];
#pragma unroll
            for (int o = 16; o > 0; o >>= 1) p += __shfl_xor_sync(0xffffffffu, p, o);
            if (tid == 0) out[0] = 1.0f / (1.0f + expf(-(p + b_out[0])));
        }
    }
}

// ---------------------------------------------------------------------------
extern "C" void kernel_launch(void* const* d_in, const int* in_sizes, int n_in,
                              void* d_out, int out_size) {
    const float* x     = (const float*)d_in[0];
    const float* vals  = (const float*)d_in[1];
    const float* W1    = (const float*)d_in[2];
    const float* W2    = (const float*)d_in[3];
    const float* w_out = (const float*)d_in[4];
    const float* b_out = (const float*)d_in[5];
    const int*   rows  = (const int*)d_in[6];
    const int*   cols  = (const int*)d_in[7];

    int n = in_sizes[0] / D_IN;   // 100000
    int e = in_sizes[1];          // 3200000

    gemm1_kernel<<<(n + 255) / 256, 256>>>(x, W1, n, cols, vals, e);
    {
        long long work = (long long)e * 4;
        int blocks = (int)((work + 255) / 256);
        edge_kernel<<<blocks, 256>>>(rows, cols, vals, e);
    }
    reduce_final_kernel<<<1024, 256>>>(n, W2, w_out, b_out, (float*)d_out);
}

// round 4
// speedup vs baseline: 1.1370x; 1.1370x over previous
#include <cuda_runtime.h>
#include <cuda_bf16.h>
#include <math.h>

#define N_NODES_MAX 100000
#define D_IN        256
#define H1          16
#define H2          32
#define KT          32     // k-tile for gemm1
#define GROWS       256    // rows per block in gemm1

// Scratch (device globals — BSS zero-init; every call leaves them zeroed again,
// so the kernel is deterministic across graph replays).
__device__ __align__(256) float g_y[N_NODES_MAX * H1];   // x @ W1
__device__ __align__(256) float g_a[N_NODES_MAX * H1];   // spmm accumulator (pre-relu)
__device__ __align__(256) float g_s[N_NODES_MAX];        // s[j] = sum_{e: col==j} val[e]
__device__ __align__(256) float g_t[H1];                 // t = sum_i s[i]*relu(a[i])
__device__ unsigned g_ticket;                            // last-block ticket

// ---------------------------------------------------------------------------
// y = x @ W1   (N x 256) @ (256 x 16)
// Staged through shared: coalesced x loads, transposed pad-257 tile (bank-
// conflict-free), W1 broadcast from shared. One row per thread for compute.
// ---------------------------------------------------------------------------
__global__ void gemm1_kernel(const float* __restrict__ x,
                             const float* __restrict__ W1, int n) {
    extern __shared__ float smem[];
    float* sW = smem;                    // [D_IN*H1] = 4096 floats
    float* sx = smem + D_IN * H1;        // [KT][257] transposed x tile

    int tid = threadIdx.x;
    for (int i = tid; i < D_IN * H1 / 4; i += GROWS)
        reinterpret_cast<float4*>(sW)[i] = reinterpret_cast<const float4*>(W1)[i];

    int row0 = blockIdx.x * GROWS;
    float acc[H1];
#pragma unroll
    for (int f = 0; f < H1; f++) acc[f] = 0.0f;

    for (int kt = 0; kt < D_IN; kt += KT) {
        __syncthreads();   // protect sx (prev iter reads / W load on iter 0)
        // Load tile: 256 rows x 32 floats = 2048 float4; 8 per thread.
        // idx -> (row = idx>>3, kv = idx&7): lanes 0..7 contiguous in a row.
#pragma unroll
        for (int i = 0; i < (GROWS * KT / 4) / GROWS; i++) {
            int idx = tid + i * GROWS;
            int r = idx >> 3, kv = idx & 7;
            if (row0 + r < n) {
                float4 v = __ldg(reinterpret_cast<const float4*>(
                    x + (size_t)(row0 + r) * D_IN + kt + kv * 4));
                int k = kv * 4;
                sx[(k + 0) * 257 + r] = v.x;
                sx[(k + 1) * 257 + r] = v.y;
                sx[(k + 2) * 257 + r] = v.z;
                sx[(k + 3) * 257 + r] = v.w;
            }
        }
        __syncthreads();
        // Compute: this thread's row = row0 + tid
#pragma unroll
        for (int kk = 0; kk < KT; kk++) {
            float xs = sx[kk * 257 + tid];
            const float4* w = reinterpret_cast<const float4*>(sW + (kt + kk) * H1);
            float4 w0 = w[0], w1 = w[1], w2 = w[2], w3 = w[3];
            acc[0]  += xs * w0.x; acc[1]  += xs * w0.y; acc[2]  += xs * w0.z; acc[3]  += xs * w0.w;
            acc[4]  += xs * w1.x; acc[5]  += xs * w1.y; acc[6]  += xs * w1.z; acc[7]  += xs * w1.w;
            acc[8]  += xs * w2.x; acc[9]  += xs * w2.y; acc[10] += xs * w2.z; acc[11] += xs * w2.w;
            acc[12] += xs * w3.x; acc[13] += xs * w3.y; acc[14] += xs * w3.z; acc[15] += xs * w3.w;
        }
    }
    int row = row0 + tid;
    if (row < n) {
        float4* yr = reinterpret_cast<float4*>(g_y + (size_t)row * H1);
        yr[0] = make_float4(acc[0],  acc[1],  acc[2],  acc[3]);
        yr[1] = make_float4(acc[4],  acc[5],  acc[6],  acc[7]);
        yr[2] = make_float4(acc[8],  acc[9],  acc[10], acc[11]);
        yr[3] = make_float4(acc[12], acc[13], acc[14], acc[15]);
    }
}

// ---------------------------------------------------------------------------
// Edge pass: a[r] += v * y[c] via red.global.add.v4.f32 (4 lanes per edge)
//            s[c] += v (lane 0 of each quad)
// ---------------------------------------------------------------------------
__global__ void edge_kernel(const int* __restrict__ rows,
                            const int* __restrict__ cols,
                            const float* __restrict__ vals, int e_count) {
    int gid = blockIdx.x * blockDim.x + threadIdx.x;
    int q = gid & 3;           // quarter of the 16-wide feature row
    int e = gid >> 2;
    if (e >= e_count) return;

    int r = __ldg(rows + e);
    int c = __ldg(cols + e);
    float v = __ldg(vals + e);

    const float4 yv = __ldg(reinterpret_cast<const float4*>(g_y + (size_t)c * H1 + q * 4));
    float px = v * yv.x, py = v * yv.y, pz = v * yv.z, pw = v * yv.w;
    float* dst = g_a + (size_t)r * H1 + q * 4;
    asm volatile("red.global.add.v4.f32 [%0], {%1, %2, %3, %4};"
                 :: "l"(dst), "f"(px), "f"(py), "f"(pz), "f"(pw) : "memory");
    if (q == 0) atomicAdd(&g_s[c], v);
}

// ---------------------------------------------------------------------------
// t[f] = sum_i s[i] * relu(a[i][f]); self-cleans g_a/g_s; last block computes
// the final output and cleans g_t/g_ticket.
// ---------------------------------------------------------------------------
__global__ void reduce_final_kernel(int n,
                                    const float* __restrict__ W2,
                                    const float* __restrict__ w_out,
                                    const float* __restrict__ b_out,
                                    float* __restrict__ out) {
    __shared__ float4 red[256];
    __shared__ bool is_last;
    int tid = threadIdx.x;
    int g = tid & 3;  // feature group: covers features [4g, 4g+4)
    const float4 z4 = {0.f, 0.f, 0.f, 0.f};
    float4 acc = z4;
    int total = n * 4;
    int stride = gridDim.x * blockDim.x;
    for (int idx = blockIdx.x * blockDim.x + tid; idx < total; idx += stride) {
        int i = idx >> 2;
        float4* ap = reinterpret_cast<float4*>(g_a + (size_t)i * H1 + g * 4);
        float4 av = *ap;
        float s = 0.0f;
        if (g == 0) { s = g_s[i]; g_s[i] = 0.0f; }   // sole reader of g_s[i]
        s = __shfl_sync(0xffffffffu, s, (tid & 31) & ~3);
        *ap = z4;                                     // self-clean g_a
        acc.x += s * fmaxf(av.x, 0.f);
        acc.y += s * fmaxf(av.y, 0.f);
        acc.z += s * fmaxf(av.z, 0.f);
        acc.w += s * fmaxf(av.w, 0.f);
    }
    red[tid] = acc;
    __syncthreads();
#pragma unroll
    for (int off = 128; off >= 4; off >>= 1) {
        if (tid < off) {
            float4 o = red[tid + off];
            red[tid].x += o.x; red[tid].y += o.y; red[tid].z += o.z; red[tid].w += o.w;
        }
        __syncthreads();
    }
    if (tid < 4) {
        float4 r4 = red[tid];
        float* dst = g_t + tid * 4;
        asm volatile("red.global.add.v4.f32 [%0], {%1, %2, %3, %4};"
                     :: "l"(dst), "f"(r4.x), "f"(r4.y), "f"(r4.z), "f"(r4.w) : "memory");
    }
    __threadfence();
    if (tid == 0) {
        unsigned done = atomicAdd(&g_ticket, 1u);
        is_last = (done == gridDim.x - 1);
    }
    __syncthreads();
    if (is_last) {
        __threadfence();  // pair with producers' fences
        float z = 0.0f;
        if (tid < H2) {
#pragma unroll
            for (int fi = 0; fi < H1; fi++) z += g_t[fi] * W2[fi * H2 + tid];
        }
        __syncthreads();
        if (tid < H1) g_t[tid] = 0.0f;   // self-clean g_t
        if (tid == 0) g_ticket = 0u;     // self-clean ticket
        if (tid < H2) {
            float p = z * w_out[tid];
#pragma unroll
            for (int o = 16; o > 0; o >>= 1) p += __shfl_xor_sync(0xffffffffu, p, o);
            if (tid == 0) out[0] = 1.0f / (1.0f + expf(-(p + b_out[0])));
        }
    }
}

// ---------------------------------------------------------------------------
extern "C" void kernel_launch(void* const* d_in, const int* in_sizes, int n_in,
                              void* d_out, int out_size) {
    const float* x     = (const float*)d_in[0];
    const float* vals  = (const float*)d_in[1];
    const float* W1    = (const float*)d_in[2];
    const float* W2    = (const float*)d_in[3];
    const float* w_out = (const float*)d_in[4];
    const float* b_out = (const float*)d_in[5];
    const int*   rows  = (const int*)d_in[6];
    const int*   cols  = (const int*)d_in[7];

    int n = in_sizes[0] / D_IN;   // 100000
    int e = in_sizes[1];          // 3200000

    int smem_bytes = (D_IN * H1 + KT * 257) * sizeof(float);  // 49280 B
    cudaFuncSetAttribute(gemm1_kernel,
                         cudaFuncAttributeMaxDynamicSharedMemorySize, smem_bytes);

    gemm1_kernel<<<(n + GROWS - 1) / GROWS, GROWS, smem_bytes>>>(x, W1, n);
    {
        long long work = (long long)e * 4;
        int blocks = (int)((work + 255) / 256);
        edge_kernel<<<blocks, 256>>>(rows, cols, vals, e);
    }
    reduce_final_kernel<<<1024, 256>>>(n, W2, w_out, b_out, (float*)d_out);
}